// round 17
// baseline (speedup 1.0000x reference)
#include <cuda_runtime.h>
#include <cuda_fp16.h>
#include <math.h>
#include <cstdint>

#define kS  1024
#define kB  4
#define kD  1024
#define kH  16
#define kDH 64

// fp16 scratch
__device__ __half g_qa[kS*kB*kD], g_ka[kS*kB*kD], g_va[kS*kB*kD];  // activations
__device__ __half g_wqkv[3][kH*kDH*kD];                            // [which][h*64+n][k]
__device__ __half g_oa[kS*kB*kD];                                  // attn out (concat)
__device__ __half g_wo[kD*kD];                                     // [n][k]
__device__ __half g_qp[kB*kH*kS*kDH];                              // [b][h][s][dh]
__device__ __half g_kp[kB*kH*kS*kDH];                              // [b][h][s][dh]
__device__ __half g_vp[kB*kH*kS*kDH];                              // [b][h][dh][s]

// ===================== helpers =====================
__device__ __forceinline__ uint32_t smem_u32(const void* p) {
    uint32_t a;
    asm("{ .reg .u64 t; cvta.to.shared.u64 t, %1; cvt.u32.u64 %0, t; }" : "=r"(a) : "l"(p));
    return a;
}
__device__ __forceinline__ void ldmatrix_x4(uint32_t* r, uint32_t a) {
    asm volatile("ldmatrix.sync.aligned.m8n8.x4.shared.b16 {%0,%1,%2,%3}, [%4];"
        : "=r"(r[0]), "=r"(r[1]), "=r"(r[2]), "=r"(r[3]) : "r"(a));
}
__device__ __forceinline__ void mma_f16(float* c, const uint32_t* a, const uint32_t* b) {
    asm volatile("mma.sync.aligned.m16n8k16.row.col.f32.f16.f16.f32 "
        "{%0,%1,%2,%3},{%4,%5,%6,%7},{%8,%9},{%0,%1,%2,%3};"
        : "+f"(c[0]), "+f"(c[1]), "+f"(c[2]), "+f"(c[3])
        : "r"(a[0]), "r"(a[1]), "r"(a[2]), "r"(a[3]), "r"(b[0]), "r"(b[1]));
}
__device__ __forceinline__ uint32_t pack_h2(float x, float y) {
    __half2 h = __floats2half2_rn(x, y);
    return *(uint32_t*)&h;
}
__device__ __forceinline__ void cp_async16(uint32_t saddr, const void* gptr) {
    asm volatile("cp.async.cg.shared.global [%0], [%1], 16;" :: "r"(saddr), "l"(gptr));
}
#define CP_COMMIT() asm volatile("cp.async.commit_group;" ::: "memory")
#define CP_WAIT_0() asm volatile("cp.async.wait_group 0;" ::: "memory")

// swizzled offset within a 128B-row tile: row-major, seg XOR (row&7)
__device__ __forceinline__ uint32_t sw_off(int row, int seg) {
    return (uint32_t)(row * 128 + ((seg ^ (row & 7)) << 4));
}

// ===========================================================================
// Prep 1: convert q/k/v activations to fp16. grid (n4/256, 3)
// ===========================================================================
__global__ void __launch_bounds__(256) cvt3_kernel(
    const float* __restrict__ q, const float* __restrict__ k,
    const float* __restrict__ v, int n4)
{
    int which = blockIdx.y;
    const float* src = (which == 0) ? q : (which == 1) ? k : v;
    __half* dst = (which == 0) ? g_qa : (which == 1) ? g_ka : g_va;
    int i = blockIdx.x * blockDim.x + threadIdx.x;
    if (i >= n4) return;
    float4 vv = ((const float4*)src)[i];
    *(uint2*)(dst + (size_t)i * 4) =
        make_uint2(pack_h2(vv.x, vv.y), pack_h2(vv.z, vv.w));
}

// ===========================================================================
// Prep 2: transpose weights to fp16 [n][k]
// ===========================================================================
__global__ void __launch_bounds__(256) transpose_wqkv_kernel(
    const float* __restrict__ Wq, const float* __restrict__ Wk,
    const float* __restrict__ Wv)
{
    __shared__ float tile[32][33];
    int which = blockIdx.z >> 4;
    int h = blockIdx.z & 15;
    const float* src = ((which == 0) ? Wq : (which == 1) ? Wk : Wv) + (size_t)h * kD * kDH;
    __half* dst = g_wqkv[which] + (size_t)h * kDH * kD;
    int c0 = blockIdx.x * 32, r0 = blockIdx.y * 32;
    int tx = threadIdx.x, ty = threadIdx.y;
    #pragma unroll
    for (int i = 0; i < 4; i++)
        tile[ty + i * 8][tx] = src[(size_t)(r0 + ty + i * 8) * kDH + c0 + tx];
    __syncthreads();
    #pragma unroll
    for (int i = 0; i < 4; i++)
        dst[(size_t)(c0 + ty + i * 8) * kD + r0 + tx] = __float2half_rn(tile[tx][ty + i * 8]);
}

__global__ void __launch_bounds__(256) transpose_wo_kernel(const float* __restrict__ Wo)
{
    __shared__ float tile[32][33];
    int c0 = blockIdx.x * 32, r0 = blockIdx.y * 32;
    int tx = threadIdx.x, ty = threadIdx.y;
    #pragma unroll
    for (int i = 0; i < 4; i++)
        tile[ty + i * 8][tx] = Wo[(size_t)(r0 + ty + i * 8) * kD + c0 + tx];
    __syncthreads();
    #pragma unroll
    for (int i = 0; i < 4; i++)
        g_wo[(size_t)(c0 + ty + i * 8) * kD + r0 + tx] = __float2half_rn(tile[tx][ty + i * 8]);
}

// ===========================================================================
// fp16 single-pass GEMM: BM=128, BN=128, BK=64, 256 thr (8 warps 4x2,
// warp tile 32x64). Stage: A 128 rows (16KB) @0, B 128 rows (16KB) @16384;
// 2 stages = 64KB. 1 sync/chunk (wait -> sync -> load(c+1) -> compute(c)).
// ===========================================================================
#define F_A 0
#define F_B 16384
#define F_STG 32768
#define FGEMM_SMEM (2 * F_STG)   // 65536

__device__ __forceinline__ void f16_compute_chunk(
    uint32_t stb, int wm, int wn, int lane, float acc[2][8][4])
{
    int lrow = lane & 15;
    int lseg = lane >> 4;
    #pragma unroll
    for (int ks = 0; ks < 4; ks++) {
        int seg = ks * 2 + lseg;
        uint32_t af[2][4];
        #pragma unroll
        for (int mt = 0; mt < 2; mt++)
            ldmatrix_x4(af[mt], stb + F_A + sw_off(wm * 32 + mt * 16 + lrow, seg));
        #pragma unroll
        for (int nt2 = 0; nt2 < 4; nt2++) {
            uint32_t t[4];
            ldmatrix_x4(t, stb + F_B + sw_off(wn * 64 + nt2 * 16 + lrow, seg));
            uint32_t b0[2] = {t[0], t[2]}, b1[2] = {t[1], t[3]};
            #pragma unroll
            for (int mt = 0; mt < 2; mt++) {
                mma_f16(acc[mt][nt2 * 2 + 0], af[mt], b0);
                mma_f16(acc[mt][nt2 * 2 + 1], af[mt], b1);
            }
        }
    }
}

// ---- fused projections, 2 heads per CTA. grid (8, 24, 4): y = which*8 + hp ----
__global__ void __launch_bounds__(256, 2) proj_mma_kernel(
    const float* __restrict__ bq, const float* __restrict__ bk,
    const float* __restrict__ bv)
{
    extern __shared__ char smem[];
    uint32_t sbase = smem_u32(smem);
    int s0 = blockIdx.x * 128;
    int which = blockIdx.y >> 3;
    int hp = blockIdx.y & 7;          // head pair: heads 2hp, 2hp+1
    int b  = blockIdx.z;
    int tid = threadIdx.x;
    int wid = tid >> 5, lane = tid & 31;
    int wm = wid >> 1, wn = wid & 1;  // warp tile 32(M) x 64(N)

    const __half* ap = (which == 0) ? g_qa : (which == 1) ? g_ka : g_va;
    const __half* wp = g_wqkv[which];
    const float* bias = (which == 0) ? bq : (which == 1) ? bk : bv;

    float acc[2][8][4];
    #pragma unroll
    for (int mt = 0; mt < 2; mt++)
        #pragma unroll
        for (int nt = 0; nt < 8; nt++)
            #pragma unroll
            for (int e = 0; e < 4; e++) acc[mt][nt][e] = 0.f;

    auto load_chunk = [&](int c, int stg) {
        uint32_t stb = sbase + stg * F_STG;
        int k0 = c * 64;
        #pragma unroll
        for (int i = 0; i < 4; i++) {
            int id = tid + i * 256;
            int m = id >> 3, k8 = id & 7;
            size_t g = ((size_t)(s0 + m) * kB + b) * kD + k0 + k8 * 8;
            cp_async16(stb + F_A + sw_off(m, k8), ap + g);
        }
        #pragma unroll
        for (int i = 0; i < 4; i++) {
            int id = tid + i * 256;
            int n = id >> 3, k8 = id & 7;
            size_t g = ((size_t)hp * 128 + n) * kD + k0 + k8 * 8;  // heads contiguous
            cp_async16(stb + F_B + sw_off(n, k8), wp + g);
        }
    };

    load_chunk(0, 0);
    CP_COMMIT();
    for (int c = 0; c < 16; c++) {
        CP_WAIT_0();
        __syncthreads();
        if (c + 1 < 16) {
            load_chunk(c + 1, (c + 1) & 1);
            CP_COMMIT();
        }
        f16_compute_chunk(sbase + (c & 1) * F_STG, wm, wn, lane, acc);
    }

    int gq = lane >> 2, tg = lane & 3;
    int h = hp * 2 + wn;              // each warp's 64 N-cols = exactly one head
    size_t bh = (size_t)b * kH + h;
    if (which < 2) {
        __half* op = (which == 0) ? g_qp : g_kp;
        #pragma unroll
        for (int mt = 0; mt < 2; mt++) {
            int row0 = s0 + wm * 32 + mt * 16 + gq;
            #pragma unroll
            for (int nt = 0; nt < 8; nt++) {
                int col = nt * 8 + tg * 2;   // within head, 0..62
                float b0 = bias[h * kDH + col], b1 = bias[h * kDH + col + 1];
                size_t off0 = (bh * kS + row0) * kDH + col;
                *(uint32_t*)(op + off0) = pack_h2(acc[mt][nt][0] + b0, acc[mt][nt][1] + b1);
                *(uint32_t*)(op + off0 + (size_t)8 * kDH) =
                    pack_h2(acc[mt][nt][2] + b0, acc[mt][nt][3] + b1);
            }
        }
    } else {
        // V transposed: [b][h][dh][s]
        #pragma unroll
        for (int mt = 0; mt < 2; mt++) {
            int row0 = s0 + wm * 32 + mt * 16 + gq;
            #pragma unroll
            for (int nt = 0; nt < 8; nt++) {
                int col = nt * 8 + tg * 2;
                float b0 = bias[h * kDH + col], b1 = bias[h * kDH + col + 1];
                float vals[4] = {acc[mt][nt][0] + b0, acc[mt][nt][1] + b1,
                                 acc[mt][nt][2] + b0, acc[mt][nt][3] + b1};
                int rr[4] = {row0, row0, row0 + 8, row0 + 8};
                int cc[4] = {col, col + 1, col, col + 1};
                #pragma unroll
                for (int e = 0; e < 4; e++)
                    g_vp[(bh * kDH + cc[e]) * kS + rr[e]] = __float2half_rn(vals[e]);
            }
        }
    }
}

// ---- output projection, BN=128. grid (32, 8) = 256 CTAs ----
__global__ void __launch_bounds__(256, 2) outproj_mma_kernel(
    const float* __restrict__ bo, float* __restrict__ out)
{
    extern __shared__ char smem[];
    uint32_t sbase = smem_u32(smem);
    int m0 = blockIdx.x * 128;
    int n0 = blockIdx.y * 128;
    int tid = threadIdx.x;
    int wid = tid >> 5, lane = tid & 31;
    int wm = wid >> 1, wn = wid & 1;

    float acc[2][8][4];
    #pragma unroll
    for (int mt = 0; mt < 2; mt++)
        #pragma unroll
        for (int nt = 0; nt < 8; nt++)
            #pragma unroll
            for (int e = 0; e < 4; e++) acc[mt][nt][e] = 0.f;

    auto load_chunk = [&](int c, int stg) {
        uint32_t stb = sbase + stg * F_STG;
        int k0 = c * 64;
        #pragma unroll
        for (int i = 0; i < 4; i++) {
            int id = tid + i * 256;
            int m = id >> 3, k8 = id & 7;
            size_t g = (size_t)(m0 + m) * kD + k0 + k8 * 8;
            cp_async16(stb + F_A + sw_off(m, k8), g_oa + g);
        }
        #pragma unroll
        for (int i = 0; i < 4; i++) {
            int id = tid + i * 256;
            int n = id >> 3, k8 = id & 7;
            size_t g = (size_t)(n0 + n) * kD + k0 + k8 * 8;
            cp_async16(stb + F_B + sw_off(n, k8), g_wo + g);
        }
    };

    load_chunk(0, 0);
    CP_COMMIT();
    for (int c = 0; c < 16; c++) {
        CP_WAIT_0();
        __syncthreads();
        if (c + 1 < 16) {
            load_chunk(c + 1, (c + 1) & 1);
            CP_COMMIT();
        }
        f16_compute_chunk(sbase + (c & 1) * F_STG, wm, wn, lane, acc);
    }

    int gq = lane >> 2, tg = lane & 3;
    #pragma unroll
    for (int mt = 0; mt < 2; mt++) {
        int row = m0 + wm * 32 + mt * 16 + gq;
        #pragma unroll
        for (int nt = 0; nt < 8; nt++) {
            int col = n0 + wn * 64 + nt * 8 + tg * 2;
            float b0 = bo[col], b1 = bo[col + 1];
            size_t r0 = (size_t)row * kD + col;
            *(float2*)(out + r0) = make_float2(acc[mt][nt][0] + b0, acc[mt][nt][1] + b1);
            *(float2*)(out + r0 + 8 * kD) = make_float2(acc[mt][nt][2] + b0, acc[mt][nt][3] + b1);
        }
    }
}

// ===========================================================================
// fp16 single-pass attention (unchanged from round 16).
// Stage (16KB): K 64x128B @0, Vt 64x128B @8192. 2 stages = 32KB; mask 4KB.
// ===========================================================================
#define A_K 0
#define A_V 8192
#define ASTG 16384
#define AMK  32768
#define ATTN_SMEM (32768 + 4096)

__global__ void __launch_bounds__(256) attn_mma_kernel(const int* __restrict__ mask)
{
    extern __shared__ char smem[];
    uint32_t sbase = smem_u32(smem);
    int s0 = blockIdx.x * 128;
    int h  = blockIdx.y;
    int b  = blockIdx.z;
    int tid = threadIdx.x;
    int w = tid >> 5, lane = tid & 31;
    int gq = lane >> 2, tg = lane & 3;
    size_t bh = (size_t)b * kH + h;

    const __half* qp = g_qp + bh * kS * kDH;
    const __half* kp = g_kp + bh * kS * kDH;
    const __half* vt = g_vp + bh * kDH * kS;   // [dh][s]

    // ---- mask preload ----
    float* Mk = (float*)(smem + AMK);
    for (int idx = tid; idx < kS; idx += 256)
        Mk[idx] = (float)mask[(size_t)idx * kB + b] * 1e18f;

    // ---- stage Q tile (128 rows x 128B, spans both stages) ----
    #pragma unroll
    for (int i = 0; i < 4; i++) {
        int id = tid + i * 256;
        int row = id >> 3, k8 = id & 7;
        size_t g = (size_t)(s0 + row) * kDH + k8 * 8;
        cp_async16(sbase + sw_off(row, k8), qp + g);
    }
    CP_COMMIT();
    CP_WAIT_0();
    __syncthreads();
    uint32_t qf[4][4];
    int lrow = lane & 15, lseg = lane >> 4;
    #pragma unroll
    for (int ks = 0; ks < 4; ks++)
        ldmatrix_x4(qf[ks], sbase + sw_off(w * 16 + lrow, ks * 2 + lseg));
    __syncthreads();  // Q reads done before stage reuse

    float acc_o[8][4];
    #pragma unroll
    for (int nt = 0; nt < 8; nt++)
        #pragma unroll
        for (int e = 0; e < 4; e++) acc_o[nt][e] = 0.f;
    float l_run[2] = {0.f, 0.f};
    const float scale = 0.125f;

    auto load_tile = [&](int t, int stg) {
        uint32_t stb = sbase + stg * ASTG;
        int j0 = t * 64;
        #pragma unroll
        for (int i = 0; i < 4; i++) {
            int id = tid + (i & 1) * 256;
            int row = id >> 3, k8 = id & 7;
            if (i < 2)
                cp_async16(stb + A_K + sw_off(row, k8),
                           kp + (size_t)(j0 + row) * kDH + k8 * 8);
            else
                cp_async16(stb + A_V + sw_off(row, k8),
                           vt + (size_t)row * kS + j0 + k8 * 8);
        }
    };

    load_tile(0, 0);
    CP_COMMIT();
    for (int t = 0; t < 16; t++) {
        CP_WAIT_0();
        __syncthreads();
        if (t + 1 < 16) {
            load_tile(t + 1, (t + 1) & 1);
            CP_COMMIT();
        }
        uint32_t stb = sbase + (t & 1) * ASTG;
        int j0 = t * 64;

        // ---- S = Q K^T ----
        float ps[8][4];
        #pragma unroll
        for (int nt = 0; nt < 8; nt++)
            #pragma unroll
            for (int e = 0; e < 4; e++) ps[nt][e] = 0.f;
        #pragma unroll
        for (int ks = 0; ks < 4; ks++) {
            int seg = ks * 2 + lseg;
            #pragma unroll
            for (int nt2 = 0; nt2 < 4; nt2++) {
                uint32_t t4[4];
                ldmatrix_x4(t4, stb + A_K + sw_off(nt2 * 16 + lrow, seg));
                uint32_t b0[2] = {t4[0], t4[2]}, b1[2] = {t4[1], t4[3]};
                mma_f16(ps[nt2 * 2 + 0], qf[ks], b0);
                mma_f16(ps[nt2 * 2 + 1], qf[ks], b1);
            }
        }

        // ---- softmax weights (no running max; masked -> exactly 0) ----
        float l0 = 0.f, l1 = 0.f;
        #pragma unroll
        for (int nt = 0; nt < 8; nt++) {
            float mk0 = Mk[j0 + nt * 8 + tg * 2], mk1 = Mk[j0 + nt * 8 + tg * 2 + 1];
            float p0 = __expf(fminf(ps[nt][0] * scale - mk0, 60.f));
            float p1 = __expf(fminf(ps[nt][1] * scale - mk1, 60.f));
            float p2 = __expf(fminf(ps[nt][2] * scale - mk0, 60.f));
            float p3 = __expf(fminf(ps[nt][3] * scale - mk1, 60.f));
            l0 += p0 + p1; l1 += p2 + p3;
            ps[nt][0] = p0; ps[nt][1] = p1; ps[nt][2] = p2; ps[nt][3] = p3;
        }
        l_run[0] += l0; l_run[1] += l1;

        // ---- O += P V (P packed to fp16 in regs) ----
        #pragma unroll
        for (int ks = 0; ks < 4; ks++) {
            uint32_t pa[4];
            pa[0] = pack_h2(ps[2 * ks + 0][0], ps[2 * ks + 0][1]);
            pa[1] = pack_h2(ps[2 * ks + 0][2], ps[2 * ks + 0][3]);
            pa[2] = pack_h2(ps[2 * ks + 1][0], ps[2 * ks + 1][1]);
            pa[3] = pack_h2(ps[2 * ks + 1][2], ps[2 * ks + 1][3]);
            int seg = ks * 2 + lseg;
            #pragma unroll
            for (int nd2 = 0; nd2 < 4; nd2++) {
                uint32_t t4[4];
                ldmatrix_x4(t4, stb + A_V + sw_off(nd2 * 16 + lrow, seg));
                uint32_t b0[2] = {t4[0], t4[2]}, b1[2] = {t4[1], t4[3]};
                mma_f16(acc_o[nd2 * 2 + 0], pa, b0);
                mma_f16(acc_o[nd2 * 2 + 1], pa, b1);
            }
        }
    }

    // ---- normalize and write fp16 concat output ----
    #pragma unroll
    for (int off = 1; off <= 2; off <<= 1) {
        l_run[0] += __shfl_xor_sync(0xffffffffu, l_run[0], off);
        l_run[1] += __shfl_xor_sync(0xffffffffu, l_run[1], off);
    }
    float inv0 = 1.0f / l_run[0], inv1 = 1.0f / l_run[1];

    int srow = s0 + w * 16 + gq;
    size_t m0r = ((size_t)srow * kB + b) * kD + (size_t)h * kDH;
    size_t m1r = ((size_t)(srow + 8) * kB + b) * kD + (size_t)h * kDH;
    #pragma unroll
    for (int nt = 0; nt < 8; nt++) {
        int col = nt * 8 + tg * 2;
        *(uint32_t*)(g_oa + m0r + col) = pack_h2(acc_o[nt][0] * inv0, acc_o[nt][1] * inv0);
        *(uint32_t*)(g_oa + m1r + col) = pack_h2(acc_o[nt][2] * inv1, acc_o[nt][3] * inv1);
    }
}

// ---------------------------------------------------------------------------
extern "C" void kernel_launch(void* const* d_in, const int* in_sizes, int n_in,
                              void* d_out, int out_size) {
    (void)in_sizes; (void)n_in; (void)out_size;
    const float* query = (const float*)d_in[0];
    const float* key   = (const float*)d_in[1];
    const float* value = (const float*)d_in[2];
    const int*   kmask = (const int*)  d_in[3];
    const float* Wq    = (const float*)d_in[4];
    const float* bq    = (const float*)d_in[5];
    const float* Wk    = (const float*)d_in[6];
    const float* bk    = (const float*)d_in[7];
    const float* Wv    = (const float*)d_in[8];
    const float* bvp   = (const float*)d_in[9];
    const float* Wo    = (const float*)d_in[10];
    const float* bo    = (const float*)d_in[11];
    float* out = (float*)d_out;

    cudaFuncSetAttribute(proj_mma_kernel, cudaFuncAttributeMaxDynamicSharedMemorySize, FGEMM_SMEM);
    cudaFuncSetAttribute(outproj_mma_kernel, cudaFuncAttributeMaxDynamicSharedMemorySize, FGEMM_SMEM);
    cudaFuncSetAttribute(attn_mma_kernel, cudaFuncAttributeMaxDynamicSharedMemorySize, ATTN_SMEM);

    const int n4_act = kS * kB * kD / 4;

    cvt3_kernel<<<dim3(n4_act / 256, 3), 256>>>(query, key, value, n4_act);
    transpose_wqkv_kernel<<<dim3(kDH / 32, kD / 32, 3 * kH), dim3(32, 8)>>>(Wq, Wk, Wv);
    transpose_wo_kernel<<<dim3(kD / 32, kD / 32), dim3(32, 8)>>>(Wo);

    proj_mma_kernel<<<dim3(kS / 128, 3 * 8, kB), 256, FGEMM_SMEM>>>(bq, bk, bvp);

    attn_mma_kernel<<<dim3(kS / 128, kH, kB), 256, ATTN_SMEM>>>(kmask);

    outproj_mma_kernel<<<dim3((kS * kB) / 128, kD / 128), 256, FGEMM_SMEM>>>(bo, out);
}